// round 4
// baseline (speedup 1.0000x reference)
#include <cuda_runtime.h>
#include <cuda_bf16.h>

#define N_NODES   100000
#define N_EDGES   1600000
#define N_GRAPHS  1000
#define IN_DIM    100
#define HID       128
#define CAP       96

// ---------------- scratch (device globals; no allocation) ----------------
__device__ int   g_cnt_in[N_NODES];
__device__ float g_dinv[N_NODES];
__device__ int   g_bucket[(size_t)N_NODES * CAP];
__device__ __nv_bfloat16 g_bufA[(size_t)N_NODES * HID];
__device__ __nv_bfloat16 g_bufB[(size_t)N_NODES * HID];
__device__ float g_psum[N_GRAPHS * 2];
__device__ float g_cnt[N_GRAPHS];

// ---------------- helpers ----------------
__device__ __forceinline__ float4 load4(const float* p) { return *(const float4*)p; }
__device__ __forceinline__ float4 load4(const __nv_bfloat16* p) {
    uint2 u = *(const uint2*)p;
    float2 f0 = __bfloat1622float2(*reinterpret_cast<__nv_bfloat162*>(&u.x));
    float2 f1 = __bfloat1622float2(*reinterpret_cast<__nv_bfloat162*>(&u.y));
    return make_float4(f0.x, f0.y, f1.x, f1.y);
}

__device__ __forceinline__ unsigned f2tf32(float x) {
    unsigned r;
    asm("cvt.rna.tf32.f32 %0, %1;" : "=r"(r) : "f"(x));
    return r;
}

__device__ __forceinline__ void mma_tf32(float* c, const unsigned* a, const unsigned* b) {
    asm volatile(
        "mma.sync.aligned.m16n8k8.row.col.f32.tf32.tf32.f32 "
        "{%0,%1,%2,%3}, {%4,%5,%6,%7}, {%8,%9}, {%0,%1,%2,%3};\n"
        : "+f"(c[0]), "+f"(c[1]), "+f"(c[2]), "+f"(c[3])
        : "r"(a[0]), "r"(a[1]), "r"(a[2]), "r"(a[3]), "r"(b[0]), "r"(b[1]));
}

// permuted k-index within a 32-wide chunk: pairs (k, k+4) adjacent
__device__ __forceinline__ int kperm(int k) {
    return (k & 24) + ((k & 3) << 1) + ((k >> 2) & 1);
}

// ---------------- setup kernels ----------------
__global__ void k_init() {
    int i = blockIdx.x * blockDim.x + threadIdx.x;
    if (i < N_NODES) g_cnt_in[i] = 0;
    if (i < N_GRAPHS) {
        g_cnt[i] = 0.f;
        g_psum[2 * i] = 0.f;
        g_psum[2 * i + 1] = 0.f;
    }
}

__global__ void k_fill(const int* __restrict__ ei) {
    int e4 = (blockIdx.x * blockDim.x + threadIdx.x) * 4;
    if (e4 >= N_EDGES) return;
    int4 s = *(const int4*)&ei[e4];
    int4 d = *(const int4*)&ei[N_EDGES + e4];
    int p0 = atomicAdd(&g_cnt_in[d.x], 1);
    int p1 = atomicAdd(&g_cnt_in[d.y], 1);
    int p2 = atomicAdd(&g_cnt_in[d.z], 1);
    int p3 = atomicAdd(&g_cnt_in[d.w], 1);
    if (p0 < CAP) g_bucket[(size_t)d.x * CAP + p0] = s.x;
    if (p1 < CAP) g_bucket[(size_t)d.y * CAP + p1] = s.y;
    if (p2 < CAP) g_bucket[(size_t)d.z * CAP + p2] = s.z;
    if (p3 < CAP) g_bucket[(size_t)d.w * CAP + p3] = s.w;
}

__global__ void k_dinv() {
    int i = blockIdx.x * blockDim.x + threadIdx.x;
    if (i < N_NODES) g_dinv[i] = rsqrtf((float)(g_cnt_in[i] + 1));
}

// ---------------- tf32 MMA GEMM: Y[N,128](bf16) = X[N,K] @ W[K,128] ----------------
// Block 256 = 8 warps (2x4), block tile 128x128, warp tile 64x32.
// smem holds tf32-converted, k-permuted tiles; B transposed -> all frag loads LDS.64.
#define SSTRIDE 36
template <int K, typename Tin>
__global__ void __launch_bounds__(256, 2)
k_gemm_mma(const Tin* __restrict__ X, const float* __restrict__ W,
           __nv_bfloat16* __restrict__ Y) {
    __shared__ unsigned sx[128 * SSTRIDE];   // [row][perm(k)]
    __shared__ unsigned sb[128 * SSTRIDE];   // [n][perm(k)]  (transposed W)

    const int tid  = threadIdx.x;
    const int lane = tid & 31, warp = tid >> 5;
    const int wm = warp >> 2;
    const int wn = warp & 3;
    const int g = lane >> 2, tig = lane & 3;
    const int m0 = blockIdx.x * 128;

    float acc[4][4][4];
#pragma unroll
    for (int mi = 0; mi < 4; mi++)
#pragma unroll
        for (int ni = 0; ni < 4; ni++)
#pragma unroll
            for (int j = 0; j < 4; j++) acc[mi][ni][j] = 0.f;

    for (int c0 = 0; c0 < K; c0 += 32) {
        __syncthreads();
        // load X tile: 128 rows x 32 cols, convert to tf32, permuted store
#pragma unroll
        for (int i = 0; i < 4; i++) {
            int idx = tid + i * 256;          // 0..1023
            int row = idx >> 3;
            int kq  = idx & 7;                // 4-col group
            int k   = c0 + kq * 4;
            int m   = m0 + row;
            float4 v = make_float4(0.f, 0.f, 0.f, 0.f);
            if (m < N_NODES && k < K)
                v = load4(&X[(size_t)m * K + k]);
            unsigned* p = &sx[row * SSTRIDE];
            p[kperm(kq * 4 + 0)] = f2tf32(v.x);
            p[kperm(kq * 4 + 1)] = f2tf32(v.y);
            p[kperm(kq * 4 + 2)] = f2tf32(v.z);
            p[kperm(kq * 4 + 3)] = f2tf32(v.w);
        }
        // load W chunk 32 x 128, store transposed [n][perm(k)], tf32
#pragma unroll
        for (int i = 0; i < 4; i++) {
            int idx = tid + i * 256;
            int r  = idx >> 5;                // k-row within chunk
            int n  = (idx & 31) * 4;
            int kr = c0 + r;
            float4 v = make_float4(0.f, 0.f, 0.f, 0.f);
            if (kr < K) v = *(const float4*)&W[kr * 128 + n];
            int pk = kperm(r);
            sb[(n + 0) * SSTRIDE + pk] = f2tf32(v.x);
            sb[(n + 1) * SSTRIDE + pk] = f2tf32(v.y);
            sb[(n + 2) * SSTRIDE + pk] = f2tf32(v.z);
            sb[(n + 3) * SSTRIDE + pk] = f2tf32(v.w);
        }
        __syncthreads();

#pragma unroll
        for (int kk = 0; kk < 32; kk += 8) {
            unsigned A[4][4];
#pragma unroll
            for (int mi = 0; mi < 4; mi++) {
                int rb = wm * 64 + mi * 16;
                uint2 lo = *(const uint2*)&sx[(rb + g) * SSTRIDE + kk + 2 * tig];
                uint2 hi = *(const uint2*)&sx[(rb + g + 8) * SSTRIDE + kk + 2 * tig];
                A[mi][0] = lo.x; A[mi][2] = lo.y;
                A[mi][1] = hi.x; A[mi][3] = hi.y;
            }
            unsigned B[4][2];
#pragma unroll
            for (int ni = 0; ni < 4; ni++) {
                int nb = wn * 32 + ni * 8 + g;
                uint2 b2 = *(const uint2*)&sb[nb * SSTRIDE + kk + 2 * tig];
                B[ni][0] = b2.x; B[ni][1] = b2.y;
            }
#pragma unroll
            for (int mi = 0; mi < 4; mi++)
#pragma unroll
                for (int ni = 0; ni < 4; ni++)
                    mma_tf32(acc[mi][ni], A[mi], B[ni]);
        }
    }

#pragma unroll
    for (int mi = 0; mi < 4; mi++) {
        int row = m0 + wm * 64 + mi * 16 + g;
#pragma unroll
        for (int ni = 0; ni < 4; ni++) {
            int col = wn * 32 + ni * 8 + 2 * tig;
            if (row < N_NODES)
                *(__nv_bfloat162*)&Y[(size_t)row * 128 + col] =
                    __floats2bfloat162_rn(acc[mi][ni][0], acc[mi][ni][1]);
            if (row + 8 < N_NODES)
                *(__nv_bfloat162*)&Y[(size_t)(row + 8) * 128 + col] =
                    __floats2bfloat162_rn(acc[mi][ni][2], acc[mi][ni][3]);
        }
    }
}

// ---------------- shared gather core (8-wide unroll for MLP) ----------------
__device__ __forceinline__ float4 gather_node(const __nv_bfloat16* __restrict__ in,
                                              int node, int c, float di) {
    float4 self = load4(&in[(size_t)node * HID + c]);
    float4 acc = make_float4(di * self.x, di * self.y, di * self.z, di * self.w);

    int cnt = g_cnt_in[node];
    if (cnt > CAP) cnt = CAP;
    const int* bk = &g_bucket[(size_t)node * CAP];
    int j = 0;
    for (; j + 8 <= cnt; j += 8) {
        int4 sa = *(const int4*)&bk[j];
        int4 sb4 = *(const int4*)&bk[j + 4];
        float w0 = g_dinv[sa.x], w1 = g_dinv[sa.y], w2 = g_dinv[sa.z], w3 = g_dinv[sa.w];
        float w4 = g_dinv[sb4.x], w5 = g_dinv[sb4.y], w6 = g_dinv[sb4.z], w7 = g_dinv[sb4.w];
        float4 v0 = load4(&in[(size_t)sa.x * HID + c]);
        float4 v1 = load4(&in[(size_t)sa.y * HID + c]);
        float4 v2 = load4(&in[(size_t)sa.z * HID + c]);
        float4 v3 = load4(&in[(size_t)sa.w * HID + c]);
        float4 v4 = load4(&in[(size_t)sb4.x * HID + c]);
        float4 v5 = load4(&in[(size_t)sb4.y * HID + c]);
        float4 v6 = load4(&in[(size_t)sb4.z * HID + c]);
        float4 v7 = load4(&in[(size_t)sb4.w * HID + c]);
        acc.x += w0*v0.x + w1*v1.x + w2*v2.x + w3*v3.x + w4*v4.x + w5*v5.x + w6*v6.x + w7*v7.x;
        acc.y += w0*v0.y + w1*v1.y + w2*v2.y + w3*v3.y + w4*v4.y + w5*v5.y + w6*v6.y + w7*v7.y;
        acc.z += w0*v0.z + w1*v1.z + w2*v2.z + w3*v3.z + w4*v4.z + w5*v5.z + w6*v6.z + w7*v7.z;
        acc.w += w0*v0.w + w1*v1.w + w2*v2.w + w3*v3.w + w4*v4.w + w5*v5.w + w6*v6.w + w7*v7.w;
    }
    for (; j + 4 <= cnt; j += 4) {
        int4 s4 = *(const int4*)&bk[j];
        float w0 = g_dinv[s4.x], w1 = g_dinv[s4.y], w2 = g_dinv[s4.z], w3 = g_dinv[s4.w];
        float4 v0 = load4(&in[(size_t)s4.x * HID + c]);
        float4 v1 = load4(&in[(size_t)s4.y * HID + c]);
        float4 v2 = load4(&in[(size_t)s4.z * HID + c]);
        float4 v3 = load4(&in[(size_t)s4.w * HID + c]);
        acc.x += w0*v0.x + w1*v1.x + w2*v2.x + w3*v3.x;
        acc.y += w0*v0.y + w1*v1.y + w2*v2.y + w3*v3.y;
        acc.z += w0*v0.z + w1*v1.z + w2*v2.z + w3*v3.z;
        acc.w += w0*v0.w + w1*v1.w + w2*v2.w + w3*v3.w;
    }
    for (; j < cnt; j++) {
        int s = bk[j];
        float w = g_dinv[s];
        float4 v = load4(&in[(size_t)s * HID + c]);
        acc.x += w * v.x; acc.y += w * v.y; acc.z += w * v.z; acc.w += w * v.w;
    }
    return make_float4(di * acc.x, di * acc.y, di * acc.z, di * acc.w);
}

// ---------------- layer-1 aggregation ----------------
__global__ void k_agg(const __nv_bfloat16* __restrict__ in,
                      __nv_bfloat16* __restrict__ out,
                      const float* __restrict__ bias) {
    int node = (blockIdx.x * blockDim.x + threadIdx.x) >> 5;
    if (node >= N_NODES) return;
    int lane = threadIdx.x & 31;
    int c = lane * 4;

    float4 a = gather_node(in, node, c, g_dinv[node]);
    float ox = fmaxf(a.x + bias[c + 0], 0.f);
    float oy = fmaxf(a.y + bias[c + 1], 0.f);
    float oz = fmaxf(a.z + bias[c + 2], 0.f);
    float ow = fmaxf(a.w + bias[c + 3], 0.f);

    uint2 u;
    *(__nv_bfloat162*)&u.x = __floats2bfloat162_rn(ox, oy);
    *(__nv_bfloat162*)&u.y = __floats2bfloat162_rn(oz, ow);
    *(uint2*)&out[(size_t)node * HID + c] = u;
}

// ---------------- layer-2 aggregation fused with projection + pooling -------
__global__ void k_agg_pool(const __nv_bfloat16* __restrict__ in,
                           const float* __restrict__ bias,
                           const float* __restrict__ Wfc,
                           const int* __restrict__ batch) {
    int node = (blockIdx.x * blockDim.x + threadIdx.x) >> 5;
    if (node >= N_NODES) return;
    int lane = threadIdx.x & 31;
    int c = lane * 4;

    float4 a = gather_node(in, node, c, g_dinv[node]);
    float ox = fmaxf(a.x + bias[c + 0], 0.f);
    float oy = fmaxf(a.y + bias[c + 1], 0.f);
    float oz = fmaxf(a.z + bias[c + 2], 0.f);
    float ow = fmaxf(a.w + bias[c + 3], 0.f);

    float p0 = ox * Wfc[(c + 0) * 2] + oy * Wfc[(c + 1) * 2] +
               oz * Wfc[(c + 2) * 2] + ow * Wfc[(c + 3) * 2];
    float p1 = ox * Wfc[(c + 0) * 2 + 1] + oy * Wfc[(c + 1) * 2 + 1] +
               oz * Wfc[(c + 2) * 2 + 1] + ow * Wfc[(c + 3) * 2 + 1];
#pragma unroll
    for (int off = 16; off; off >>= 1) {
        p0 += __shfl_xor_sync(0xffffffffu, p0, off);
        p1 += __shfl_xor_sync(0xffffffffu, p1, off);
    }
    if (lane == 0) {
        int gidx = batch[node];
        atomicAdd(&g_psum[2 * gidx + 0], p0);
        atomicAdd(&g_psum[2 * gidx + 1], p1);
        atomicAdd(&g_cnt[gidx], 1.f);
    }
}

__global__ void k_final(float* __restrict__ out, const float* __restrict__ bfc) {
    int gidx = blockIdx.x * blockDim.x + threadIdx.x;
    if (gidx >= N_GRAPHS) return;
    float c = fmaxf(g_cnt[gidx], 1.f);
    out[2 * gidx + 0] = g_psum[2 * gidx + 0] / c + bfc[0];
    out[2 * gidx + 1] = g_psum[2 * gidx + 1] / c + bfc[1];
}

// ---------------- launch ----------------
extern "C" void kernel_launch(void* const* d_in, const int* in_sizes, int n_in,
                              void* d_out, int out_size) {
    const float* x     = (const float*)d_in[0];
    const int*   ei    = (const int*)d_in[1];
    const int*   batch = (const int*)d_in[2];
    const float* W1  = (const float*)d_in[4];
    const float* b1  = (const float*)d_in[5];
    const float* W2  = (const float*)d_in[6];
    const float* b2  = (const float*)d_in[7];
    const float* Wfc = (const float*)d_in[8];
    const float* bfc = (const float*)d_in[9];
    float* out = (float*)d_out;

    static cudaStream_t s_side = nullptr;
    static cudaEvent_t ev_fork = nullptr, ev_join = nullptr;
    if (!s_side) {
        cudaStreamCreateWithFlags(&s_side, cudaStreamNonBlocking);
        cudaEventCreateWithFlags(&ev_fork, cudaEventDisableTiming);
        cudaEventCreateWithFlags(&ev_join, cudaEventDisableTiming);
    }

    __nv_bfloat16 *pA = nullptr, *pB = nullptr;
    cudaGetSymbolAddress((void**)&pA, g_bufA);
    cudaGetSymbolAddress((void**)&pB, g_bufB);

    const int node_blocks = (N_NODES + 255) / 256;
    const int fill_blocks = (N_EDGES / 4 + 255) / 256;
    const int gemm_blocks = (N_NODES + 127) / 128;
    const int warp_blocks = (N_NODES * 32 + 255) / 256;

    k_init<<<node_blocks, 256>>>();
    cudaEventRecord(ev_fork, 0);
    cudaStreamWaitEvent(s_side, ev_fork, 0);
    k_fill<<<fill_blocks, 256, 0, s_side>>>(ei);
    k_dinv<<<node_blocks, 256, 0, s_side>>>();
    cudaEventRecord(ev_join, s_side);

    k_gemm_mma<IN_DIM, float><<<gemm_blocks, 256>>>(x, W1, pA);

    cudaStreamWaitEvent(0, ev_join, 0);
    k_agg<<<warp_blocks, 256>>>(pA, pB, b1);

    k_gemm_mma<HID, __nv_bfloat16><<<gemm_blocks, 256>>>(pB, W2, pA);
    k_agg_pool<<<warp_blocks, 256>>>(pA, b2, Wfc, batch);
    k_final<<<(N_GRAPHS + 255) / 256, 256>>>(out, bfc);
}

// round 6
// speedup vs baseline: 1.2936x; 1.2936x over previous
#include <cuda_runtime.h>
#include <cuda_bf16.h>
#include <cstdint>

#define N_NODES   100000
#define N_EDGES   1600000
#define N_GRAPHS  1000
#define IN_DIM    100
#define HID       128
#define CAP       96

// ---------------- scratch (device globals; no allocation) ----------------
__device__ int   g_cnt_in[N_NODES];
__device__ float g_dinv[N_NODES];
__device__ int   g_bucket[(size_t)N_NODES * CAP];
__device__ __nv_bfloat16 g_bufA[(size_t)N_NODES * HID];
__device__ __nv_bfloat16 g_bufB[(size_t)N_NODES * HID];
__device__ float g_psum[N_GRAPHS * 2];
__device__ float g_cnt[N_GRAPHS];

// ---------------- helpers ----------------
__device__ __forceinline__ float4 load4(const __nv_bfloat16* p) {
    uint2 u = *(const uint2*)p;
    float2 f0 = __bfloat1622float2(*reinterpret_cast<__nv_bfloat162*>(&u.x));
    float2 f1 = __bfloat1622float2(*reinterpret_cast<__nv_bfloat162*>(&u.y));
    return make_float4(f0.x, f0.y, f1.x, f1.y);
}

__device__ __forceinline__ unsigned packbf(float a, float b) {
    __nv_bfloat162 h = __floats2bfloat162_rn(a, b);
    return *reinterpret_cast<unsigned*>(&h);
}

// ---------------- setup kernels ----------------
__global__ void k_init() {
    int i = blockIdx.x * blockDim.x + threadIdx.x;
    if (i < N_NODES) g_cnt_in[i] = 0;
    if (i < N_GRAPHS) {
        g_cnt[i] = 0.f;
        g_psum[2 * i] = 0.f;
        g_psum[2 * i + 1] = 0.f;
    }
}

__global__ void k_fill(const int* __restrict__ ei) {
    int e4 = (blockIdx.x * blockDim.x + threadIdx.x) * 4;
    if (e4 >= N_EDGES) return;
    int4 s = *(const int4*)&ei[e4];
    int4 d = *(const int4*)&ei[N_EDGES + e4];
    int p0 = atomicAdd(&g_cnt_in[d.x], 1);
    int p1 = atomicAdd(&g_cnt_in[d.y], 1);
    int p2 = atomicAdd(&g_cnt_in[d.z], 1);
    int p3 = atomicAdd(&g_cnt_in[d.w], 1);
    if (p0 < CAP) g_bucket[(size_t)d.x * CAP + p0] = s.x;
    if (p1 < CAP) g_bucket[(size_t)d.y * CAP + p1] = s.y;
    if (p2 < CAP) g_bucket[(size_t)d.z * CAP + p2] = s.z;
    if (p3 < CAP) g_bucket[(size_t)d.w * CAP + p3] = s.w;
}

__global__ void k_dinv() {
    int i = blockIdx.x * blockDim.x + threadIdx.x;
    if (i < N_NODES) g_dinv[i] = rsqrtf((float)(g_cnt_in[i] + 1));
}

// ---------------- bf16 MMA GEMM: Y[N,128](bf16) = X[N,K] @ W[K,128] -------------
// mma.sync.m16n8k16 bf16, fp32 accum. Block 256 = 8 warps (2x4),
// block tile 128x128, warp tile 64x32, K-chunk 64.
// smem stores bf16 PAIRS as uint: sa[row][kp] (kp = k/2), sb[n][kp], pitch 36
// -> fragment reads are conflict-free ((4r+t)%32 all distinct).
// If SCALE, epilogue multiplies row r of Y by g_dinv[r].

#define PITCH 36
__device__ __forceinline__ void mma_bf16(float* c, const unsigned* a, const unsigned* b) {
    asm volatile(
        "mma.sync.aligned.m16n8k16.row.col.f32.bf16.bf16.f32 "
        "{%0,%1,%2,%3}, {%4,%5,%6,%7}, {%8,%9}, {%0,%1,%2,%3};\n"
        : "+f"(c[0]), "+f"(c[1]), "+f"(c[2]), "+f"(c[3])
        : "r"(a[0]), "r"(a[1]), "r"(a[2]), "r"(a[3]), "r"(b[0]), "r"(b[1]));
}

template <int K, bool SCALE, typename Tin>
__global__ void __launch_bounds__(256, 2)
k_gemm_mma(const Tin* __restrict__ X, const float* __restrict__ W,
           __nv_bfloat16* __restrict__ Y) {
    __shared__ unsigned sa[128 * PITCH];   // A pairs: [row][kp], kp 0..31
    __shared__ unsigned sb[128 * PITCH];   // B=W^T pairs: [n][kp]

    const int tid  = threadIdx.x;
    const int lane = tid & 31, warp = tid >> 5;
    const int wm = warp >> 2;            // m offset wm*64
    const int wn = warp & 3;             // n offset wn*32
    const int g = lane >> 2, tig = lane & 3;
    const int m0 = blockIdx.x * 128;

    float acc[4][4][4];
#pragma unroll
    for (int mi = 0; mi < 4; mi++)
#pragma unroll
        for (int ni = 0; ni < 4; ni++)
#pragma unroll
            for (int j = 0; j < 4; j++) acc[mi][ni][j] = 0.f;

    for (int c0 = 0; c0 < K; c0 += 64) {
        __syncthreads();
        // ---- A tile: 128 rows x 64 k (2048 four-k units, 8 iters) ----
#pragma unroll
        for (int i = 0; i < 8; i++) {
            int idx = tid + i * 256;
            int row = idx >> 4;           // 0..127
            int kq  = idx & 15;           // 4-k group
            int k   = c0 + kq * 4;
            int m   = m0 + row;
            uint2 st = make_uint2(0u, 0u);
            if (m < N_NODES && k < K) {
                if constexpr (sizeof(Tin) == 4) {
                    float4 v = *(const float4*)&X[(size_t)m * K + k];
                    st.x = packbf(v.x, v.y);
                    st.y = packbf(v.z, v.w);
                } else {
                    st = *(const uint2*)&X[(size_t)m * K + k];   // already bf16 pairs
                }
            }
            *(uint2*)&sa[row * PITCH + kq * 2] = st;
        }
        // ---- B tile: W^T, pairs along k. units: (kp 0..31, n4 0..31) = 1024, 4 iters ----
#pragma unroll
        for (int i = 0; i < 4; i++) {
            int idx = tid + i * 256;
            int kp = idx >> 5;            // 0..31
            int n4 = (idx & 31) * 4;
            int k  = c0 + kp * 2;
            float4 w0 = make_float4(0.f, 0.f, 0.f, 0.f);
            float4 w1 = make_float4(0.f, 0.f, 0.f, 0.f);
            if (k < K)     w0 = *(const float4*)&W[(size_t)k * 128 + n4];
            if (k + 1 < K) w1 = *(const float4*)&W[(size_t)(k + 1) * 128 + n4];
            sb[(n4 + 0) * PITCH + kp] = packbf(w0.x, w1.x);
            sb[(n4 + 1) * PITCH + kp] = packbf(w0.y, w1.y);
            sb[(n4 + 2) * PITCH + kp] = packbf(w0.z, w1.z);
            sb[(n4 + 3) * PITCH + kp] = packbf(w0.w, w1.w);
        }
        __syncthreads();

#pragma unroll
        for (int kk = 0; kk < 4; kk++) {       // 4 k16 steps per chunk
            int kp0 = kk * 8;
            unsigned A[4][4];
#pragma unroll
            for (int mi = 0; mi < 4; mi++) {
                int rb = wm * 64 + mi * 16;
                A[mi][0] = sa[(rb + g) * PITCH + kp0 + tig];
                A[mi][1] = sa[(rb + g + 8) * PITCH + kp0 + tig];
                A[mi][2] = sa[(rb + g) * PITCH + kp0 + 4 + tig];
                A[mi][3] = sa[(rb + g + 8) * PITCH + kp0 + 4 + tig];
            }
            unsigned B[4][2];
#pragma unroll
            for (int ni = 0; ni < 4; ni++) {
                int nb = wn * 32 + ni * 8 + g;
                B[ni][0] = sb[nb * PITCH + kp0 + tig];
                B[ni][1] = sb[nb * PITCH + kp0 + 4 + tig];
            }
#pragma unroll
            for (int mi = 0; mi < 4; mi++)
#pragma unroll
                for (int ni = 0; ni < 4; ni++)
                    mma_bf16(acc[mi][ni], A[mi], B[ni]);
        }
    }

#pragma unroll
    for (int mi = 0; mi < 4; mi++) {
        int row = m0 + wm * 64 + mi * 16 + g;
        float s0 = 1.f, s1 = 1.f;
        if (SCALE) {
            if (row < N_NODES) s0 = g_dinv[row];
            if (row + 8 < N_NODES) s1 = g_dinv[row + 8];
        }
#pragma unroll
        for (int ni = 0; ni < 4; ni++) {
            int col = wn * 32 + ni * 8 + 2 * tig;
            if (row < N_NODES)
                *(__nv_bfloat162*)&Y[(size_t)row * 128 + col] =
                    __floats2bfloat162_rn(acc[mi][ni][0] * s0, acc[mi][ni][1] * s0);
            if (row + 8 < N_NODES)
                *(__nv_bfloat162*)&Y[(size_t)(row + 8) * 128 + col] =
                    __floats2bfloat162_rn(acc[mi][ni][2] * s1, acc[mi][ni][3] * s1);
        }
    }
}

// ---------------- gather (with per-src dinv; for layer 1) ----------------
__device__ __forceinline__ float4 gather_node(const __nv_bfloat16* __restrict__ in,
                                              int node, int c, float di) {
    float4 self = load4(&in[(size_t)node * HID + c]);
    float4 acc = make_float4(di * self.x, di * self.y, di * self.z, di * self.w);

    int cnt = g_cnt_in[node];
    if (cnt > CAP) cnt = CAP;
    const int* bk = &g_bucket[(size_t)node * CAP];
    int j = 0;
    for (; j + 8 <= cnt; j += 8) {
        int4 sa4 = *(const int4*)&bk[j];
        int4 sb4 = *(const int4*)&bk[j + 4];
        float w0 = g_dinv[sa4.x], w1 = g_dinv[sa4.y], w2 = g_dinv[sa4.z], w3 = g_dinv[sa4.w];
        float w4 = g_dinv[sb4.x], w5 = g_dinv[sb4.y], w6 = g_dinv[sb4.z], w7 = g_dinv[sb4.w];
        float4 v0 = load4(&in[(size_t)sa4.x * HID + c]);
        float4 v1 = load4(&in[(size_t)sa4.y * HID + c]);
        float4 v2 = load4(&in[(size_t)sa4.z * HID + c]);
        float4 v3 = load4(&in[(size_t)sa4.w * HID + c]);
        float4 v4 = load4(&in[(size_t)sb4.x * HID + c]);
        float4 v5 = load4(&in[(size_t)sb4.y * HID + c]);
        float4 v6 = load4(&in[(size_t)sb4.z * HID + c]);
        float4 v7 = load4(&in[(size_t)sb4.w * HID + c]);
        acc.x += w0*v0.x + w1*v1.x + w2*v2.x + w3*v3.x + w4*v4.x + w5*v5.x + w6*v6.x + w7*v7.x;
        acc.y += w0*v0.y + w1*v1.y + w2*v2.y + w3*v3.y + w4*v4.y + w5*v5.y + w6*v6.y + w7*v7.y;
        acc.z += w0*v0.z + w1*v1.z + w2*v2.z + w3*v3.z + w4*v4.z + w5*v5.z + w6*v6.z + w7*v7.z;
        acc.w += w0*v0.w + w1*v1.w + w2*v2.w + w3*v3.w + w4*v4.w + w5*v5.w + w6*v6.w + w7*v7.w;
    }
    for (; j + 4 <= cnt; j += 4) {
        int4 s4 = *(const int4*)&bk[j];
        float w0 = g_dinv[s4.x], w1 = g_dinv[s4.y], w2 = g_dinv[s4.z], w3 = g_dinv[s4.w];
        float4 v0 = load4(&in[(size_t)s4.x * HID + c]);
        float4 v1 = load4(&in[(size_t)s4.y * HID + c]);
        float4 v2 = load4(&in[(size_t)s4.z * HID + c]);
        float4 v3 = load4(&in[(size_t)s4.w * HID + c]);
        acc.x += w0*v0.x + w1*v1.x + w2*v2.x + w3*v3.x;
        acc.y += w0*v0.y + w1*v1.y + w2*v2.y + w3*v3.y;
        acc.z += w0*v0.z + w1*v1.z + w2*v2.z + w3*v3.z;
        acc.w += w0*v0.w + w1*v1.w + w2*v2.w + w3*v3.w;
    }
    for (; j < cnt; j++) {
        int s = bk[j];
        float w = g_dinv[s];
        float4 v = load4(&in[(size_t)s * HID + c]);
        acc.x += w * v.x; acc.y += w * v.y; acc.z += w * v.z; acc.w += w * v.w;
    }
    return make_float4(di * acc.x, di * acc.y, di * acc.z, di * acc.w);
}

// ---------------- gather (rows pre-scaled by dinv[src]; for layer 2) -------
__device__ __forceinline__ float4 gather_node_ps(const __nv_bfloat16* __restrict__ in,
                                                 int node, int c, float di) {
    float4 self = load4(&in[(size_t)node * HID + c]);   // already dinv[node]-scaled
    float4 acc = self;

    int cnt = g_cnt_in[node];
    if (cnt > CAP) cnt = CAP;
    const int* bk = &g_bucket[(size_t)node * CAP];
    int j = 0;
    for (; j + 8 <= cnt; j += 8) {
        int4 sa4 = *(const int4*)&bk[j];
        int4 sb4 = *(const int4*)&bk[j + 4];
        float4 v0 = load4(&in[(size_t)sa4.x * HID + c]);
        float4 v1 = load4(&in[(size_t)sa4.y * HID + c]);
        float4 v2 = load4(&in[(size_t)sa4.z * HID + c]);
        float4 v3 = load4(&in[(size_t)sa4.w * HID + c]);
        float4 v4 = load4(&in[(size_t)sb4.x * HID + c]);
        float4 v5 = load4(&in[(size_t)sb4.y * HID + c]);
        float4 v6 = load4(&in[(size_t)sb4.z * HID + c]);
        float4 v7 = load4(&in[(size_t)sb4.w * HID + c]);
        acc.x += v0.x + v1.x + v2.x + v3.x + v4.x + v5.x + v6.x + v7.x;
        acc.y += v0.y + v1.y + v2.y + v3.y + v4.y + v5.y + v6.y + v7.y;
        acc.z += v0.z + v1.z + v2.z + v3.z + v4.z + v5.z + v6.z + v7.z;
        acc.w += v0.w + v1.w + v2.w + v3.w + v4.w + v5.w + v6.w + v7.w;
    }
    for (; j + 4 <= cnt; j += 4) {
        int4 s4 = *(const int4*)&bk[j];
        float4 v0 = load4(&in[(size_t)s4.x * HID + c]);
        float4 v1 = load4(&in[(size_t)s4.y * HID + c]);
        float4 v2 = load4(&in[(size_t)s4.z * HID + c]);
        float4 v3 = load4(&in[(size_t)s4.w * HID + c]);
        acc.x += v0.x + v1.x + v2.x + v3.x;
        acc.y += v0.y + v1.y + v2.y + v3.y;
        acc.z += v0.z + v1.z + v2.z + v3.z;
        acc.w += v0.w + v1.w + v2.w + v3.w;
    }
    for (; j < cnt; j++) {
        int s = bk[j];
        float4 v = load4(&in[(size_t)s * HID + c]);
        acc.x += v.x; acc.y += v.y; acc.z += v.z; acc.w += v.w;
    }
    return make_float4(di * acc.x, di * acc.y, di * acc.z, di * acc.w);
}

// ---------------- layer-1 aggregation ----------------
__global__ void k_agg(const __nv_bfloat16* __restrict__ in,
                      __nv_bfloat16* __restrict__ out,
                      const float* __restrict__ bias) {
    int node = (blockIdx.x * blockDim.x + threadIdx.x) >> 5;
    if (node >= N_NODES) return;
    int lane = threadIdx.x & 31;
    int c = lane * 4;

    float4 a = gather_node(in, node, c, g_dinv[node]);
    float ox = fmaxf(a.x + bias[c + 0], 0.f);
    float oy = fmaxf(a.y + bias[c + 1], 0.f);
    float oz = fmaxf(a.z + bias[c + 2], 0.f);
    float ow = fmaxf(a.w + bias[c + 3], 0.f);

    uint2 u;
    *(__nv_bfloat162*)&u.x = __floats2bfloat162_rn(ox, oy);
    *(__nv_bfloat162*)&u.y = __floats2bfloat162_rn(oz, ow);
    *(uint2*)&out[(size_t)node * HID + c] = u;
}

// ---------------- layer-2 aggregation fused with projection + pooling -------
__global__ void k_agg_pool(const __nv_bfloat16* __restrict__ in,
                           const float* __restrict__ bias,
                           const float* __restrict__ Wfc,
                           const int* __restrict__ batch) {
    int node = (blockIdx.x * blockDim.x + threadIdx.x) >> 5;
    if (node >= N_NODES) return;
    int lane = threadIdx.x & 31;
    int c = lane * 4;

    float4 a = gather_node_ps(in, node, c, g_dinv[node]);
    float ox = fmaxf(a.x + bias[c + 0], 0.f);
    float oy = fmaxf(a.y + bias[c + 1], 0.f);
    float oz = fmaxf(a.z + bias[c + 2], 0.f);
    float ow = fmaxf(a.w + bias[c + 3], 0.f);

    float p0 = ox * Wfc[(c + 0) * 2] + oy * Wfc[(c + 1) * 2] +
               oz * Wfc[(c + 2) * 2] + ow * Wfc[(c + 3) * 2];
    float p1 = ox * Wfc[(c + 0) * 2 + 1] + oy * Wfc[(c + 1) * 2 + 1] +
               oz * Wfc[(c + 2) * 2 + 1] + ow * Wfc[(c + 3) * 2 + 1];
#pragma unroll
    for (int off = 16; off; off >>= 1) {
        p0 += __shfl_xor_sync(0xffffffffu, p0, off);
        p1 += __shfl_xor_sync(0xffffffffu, p1, off);
    }
    if (lane == 0) {
        int gidx = batch[node];
        atomicAdd(&g_psum[2 * gidx + 0], p0);
        atomicAdd(&g_psum[2 * gidx + 1], p1);
        atomicAdd(&g_cnt[gidx], 1.f);
    }
}

__global__ void k_final(float* __restrict__ out, const float* __restrict__ bfc) {
    int gidx = blockIdx.x * blockDim.x + threadIdx.x;
    if (gidx >= N_GRAPHS) return;
    float c = fmaxf(g_cnt[gidx], 1.f);
    out[2 * gidx + 0] = g_psum[2 * gidx + 0] / c + bfc[0];
    out[2 * gidx + 1] = g_psum[2 * gidx + 1] / c + bfc[1];
}

// ---------------- launch ----------------
extern "C" void kernel_launch(void* const* d_in, const int* in_sizes, int n_in,
                              void* d_out, int out_size) {
    const float* x     = (const float*)d_in[0];
    const int*   ei    = (const int*)d_in[1];
    const int*   batch = (const int*)d_in[2];
    const float* W1  = (const float*)d_in[4];
    const float* b1  = (const float*)d_in[5];
    const float* W2  = (const float*)d_in[6];
    const float* b2  = (const float*)d_in[7];
    const float* Wfc = (const float*)d_in[8];
    const float* bfc = (const float*)d_in[9];
    float* out = (float*)d_out;

    static cudaStream_t s_side = nullptr;
    static cudaEvent_t ev_fork = nullptr, ev_join = nullptr;
    if (!s_side) {
        cudaStreamCreateWithFlags(&s_side, cudaStreamNonBlocking);
        cudaEventCreateWithFlags(&ev_fork, cudaEventDisableTiming);
        cudaEventCreateWithFlags(&ev_join, cudaEventDisableTiming);
    }

    __nv_bfloat16 *pA = nullptr, *pB = nullptr;
    cudaGetSymbolAddress((void**)&pA, g_bufA);
    cudaGetSymbolAddress((void**)&pB, g_bufB);

    const int node_blocks = (N_NODES + 255) / 256;
    const int fill_blocks = (N_EDGES / 4 + 255) / 256;
    const int gemm_blocks = (N_NODES + 127) / 128;
    const int warp_blocks = (N_NODES * 32 + 255) / 256;

    k_init<<<node_blocks, 256>>>();
    cudaEventRecord(ev_fork, 0);
    cudaStreamWaitEvent(s_side, ev_fork, 0);
    k_fill<<<fill_blocks, 256, 0, s_side>>>(ei);
    k_dinv<<<node_blocks, 256, 0, s_side>>>();
    cudaEventRecord(ev_join, s_side);

    // GEMM1: unscaled output (dinv not ready yet; overlaps CSR build)
    k_gemm_mma<IN_DIM, false, float><<<gemm_blocks, 256>>>(x, W1, pA);

    cudaStreamWaitEvent(0, ev_join, 0);
    k_agg<<<warp_blocks, 256>>>(pA, pB, b1);

    // GEMM2: epilogue pre-scales rows by dinv[row]
    k_gemm_mma<HID, true, __nv_bfloat16><<<gemm_blocks, 256>>>(pB, W2, pA);
    k_agg_pool<<<warp_blocks, 256>>>(pA, b2, Wfc, batch);
    k_final<<<(N_GRAPHS + 255) / 256, 256>>>(out, bfc);
}